// round 15
// baseline (speedup 1.0000x reference)
#include <cuda_runtime.h>
#include <cuda_fp16.h>
#include <cstdint>

#define BB   64
#define LL   128
#define TE   256
#define CIN  256
#define HH   512
#define CAT  768
#define G4   2048
#define OUTN 128
#define NBLK 288
#define NTHR 256

// ---------------- persistent device buffers ----------------
__device__ __half g_peh[(size_t)BB * TE * HH];   // proj_enc fp16 (16 MB)
__device__ __half g_henh[(size_t)BB * TE * HH];  // h_en fp16 (16 MB)
__device__ __half g_xh[(size_t)BB * LL * CIN];   // x fp16 (4 MB)
__device__ float g_h2[(size_t)BB * TE * CIN];    // h_en @ Wy_ctx^T (16 MB fp32)
__device__ float g_e[BB * TE];
__device__ float g_pdp[4 * 64 * HH];             // pd partials (4 slices k256)
__device__ float g_xp[64 * CIN];                 // xx partial (1 slice K=256)
__device__ float g_zp[6 * 64 * G4];              // z partials (zh:0-3, zx:4-5; epi O1)
__device__ float g_fp[6 * 64 * 3 * HH];          // cfc partials (h:0-3, x:4-5; epi O2)
__device__ float g_h[BB * HH];
__device__ float g_c[BB * HH];
// fp16 activation twins (GEMM A operands)
__device__ __half g_hh[BB * HH];
__device__ __half g_ch[BB * HH];
__device__ __half g_ctxh[BB * HH];
__device__ __half g_xhath[BB * CIN];
__device__ __half g_hlh[BB * HH];
__device__ __half g_hidh[BB * HH];
// fp16 weights
__device__ __half g_w6h[G4 * CAT];               // [W_ih | W_hh]
__device__ __half g_w3h[3 * HH * CAT];           // [ff1; ff2; ta+tb]
__device__ __half g_wdh[HH * 1024];              // W_dec
__device__ __half g_wyh[CIN * CAT];              // W_yattn
__device__ __half g_wo1h[HH * 1024];             // W_o1
__device__ __half g_wo2h[OUTN * HH];             // W_o2
__device__ __half g_wench[HH * HH];              // W_enc
__device__ float g_b3[3 * HH];
// two-level barrier state: 16 arrival counters on distinct 128B lines + gen
__device__ unsigned long long g_cnt[16 * 16];
__device__ unsigned long long g_gen;

// ---------------- helpers ----------------
__device__ __forceinline__ float fast_tanh(float x) {
    float y;
    asm("tanh.approx.f32 %0, %1;" : "=f"(y) : "f"(x));
    return y;
}
__device__ __forceinline__ float sigm(float x) {
    return 1.0f / (1.0f + __expf(-x));
}
__device__ __forceinline__ void cpa16(void* smem, const void* gmem) {
    unsigned s = (unsigned)__cvta_generic_to_shared(smem);
    asm volatile("cp.async.ca.shared.global [%0], [%1], 16;" :: "r"(s), "l"(gmem));
}

// ---------------- two-level global barrier ----------------
#define GSYNC() do {                                                           \
    __syncthreads();                                                           \
    if (threadIdx.x == 0) {                                                    \
        __threadfence();                                                       \
        bar_t += 1;                                                            \
        atomicAdd(&g_cnt[(bid & 15) * 16], 1ull);                              \
        if (bid == 0) {                                                        \
            unsigned long long target = bar_t * (unsigned long long)NBLK;      \
            for (;;) {                                                         \
                unsigned long long ssum = 0;                                   \
                _Pragma("unroll")                                              \
                for (int ii = 0; ii < 16; ii++)                                \
                    ssum += *(volatile unsigned long long*)&g_cnt[ii * 16];    \
                if (ssum >= target) break;                                     \
            }                                                                  \
            __threadfence();                                                   \
            atomicAdd(&g_gen, 1ull);                                           \
        } else {                                                               \
            while (*(volatile unsigned long long*)&g_gen < bar_t) { }          \
        }                                                                      \
        __threadfence();                                                       \
    }                                                                          \
    __syncthreads();                                                           \
} while (0)

// ---------------- shared memory ----------------
struct SmemG { __half A[64][136]; __half W[64][136]; };   // 34.8 KB
struct SmemA { float pds[HH]; float wss[HH]; float ss[TE]; float red[NTHR]; };
union Smem { SmemG g; SmemA a; };

// ---------------- mma.sync m16n8k16 fp16 -> fp32 ----------------
__device__ __forceinline__ void mma16816(float* c, unsigned a0, unsigned a1,
                                         unsigned a2, unsigned a3,
                                         unsigned b0, unsigned b1) {
    asm volatile(
        "mma.sync.aligned.m16n8k16.row.col.f32.f16.f16.f32 "
        "{%0,%1,%2,%3}, {%4,%5,%6,%7}, {%8,%9}, {%0,%1,%2,%3};"
        : "+f"(c[0]), "+f"(c[1]), "+f"(c[2]), "+f"(c[3])
        : "r"(a0), "r"(a1), "r"(a2), "r"(a3), "r"(b0), "r"(b1));
}

// ---------------- 64x64xK GEMM job, 256 threads, cp.async smem staging ---------
__device__ __noinline__ void gemm_mma(const __half* __restrict__ A, int lda,
                                      const __half* __restrict__ W, int ldw,
                                      int klen,
                                      float* __restrict__ dst, int dstr,
                                      __half* __restrict__ dsth,
                                      const float* __restrict__ bias, SmemG& s) {
    const int tid  = threadIdx.x;
    const int lane = tid & 31, wid = tid >> 5;
    const int wm = wid >> 1, wn = wid & 1;      // 4 x 2 warp grid -> m16 x n32
    const int gr = lane >> 2, kc = (lane & 3) * 2;
    const int lr = tid >> 2;                    // staging row 0..63
    const int lu = tid & 3;                     // staging unit group
    float c[4][4];
#pragma unroll
    for (int nf = 0; nf < 4; nf++)
#pragma unroll
        for (int i = 0; i < 4; i++) c[nf][i] = 0.0f;

    for (int kb = 0; kb < klen; kb += 128) {
        __syncthreads();   // previous chunk's smem reads complete
        const __half* Ar = A + (size_t)lr * lda + kb;
        const __half* Wr = W + (size_t)lr * ldw + kb;
#pragma unroll
        for (int u = 0; u < 4; u++) {
            int unit = lu + 4 * u;
            cpa16(&s.A[lr][unit * 8], Ar + unit * 8);
            cpa16(&s.W[lr][unit * 8], Wr + unit * 8);
        }
        asm volatile("cp.async.commit_group;");
        asm volatile("cp.async.wait_group 0;" ::: "memory");
        __syncthreads();
#pragma unroll
        for (int k0 = 0; k0 < 128; k0 += 16) {
            unsigned a0 = *(const unsigned*)&s.A[wm * 16 + gr][k0 + kc];
            unsigned a1 = *(const unsigned*)&s.A[wm * 16 + gr + 8][k0 + kc];
            unsigned a2 = *(const unsigned*)&s.A[wm * 16 + gr][k0 + kc + 8];
            unsigned a3 = *(const unsigned*)&s.A[wm * 16 + gr + 8][k0 + kc + 8];
#pragma unroll
            for (int nf = 0; nf < 4; nf++) {
                unsigned b0 = *(const unsigned*)&s.W[wn * 32 + nf * 8 + gr][k0 + kc];
                unsigned b1 = *(const unsigned*)&s.W[wn * 32 + nf * 8 + gr][k0 + kc + 8];
                mma16816(c[nf], a0, a1, a2, a3, b0, b1);
            }
        }
    }
    const int row = wm * 16 + gr;
#pragma unroll
    for (int nf = 0; nf < 4; nf++) {
        int col = wn * 32 + nf * 8 + kc;
        float add0 = 0.0f, add1 = 0.0f;
        if (bias) { add0 = bias[col]; add1 = bias[col + 1]; }
        float v0 = c[nf][0] + add0, v1 = c[nf][1] + add1;
        float v2 = c[nf][2] + add0, v3 = c[nf][3] + add1;
        if (dsth) {
            *(__half2*)(dsth + (size_t)row * dstr + col) = __floats2half2_rn(v0, v1);
            *(__half2*)(dsth + (size_t)(row + 8) * dstr + col) = __floats2half2_rn(v2, v3);
        } else {
            *(float2*)(dst + (size_t)row * dstr + col) = make_float2(v0, v1);
            *(float2*)(dst + (size_t)(row + 8) * dstr + col) = make_float2(v2, v3);
        }
    }
}

// ---------------- B1: e-scores for (batch b, t-chunk tc of 64) ----------------
__device__ __noinline__ void escore(int b, int tc, const float* __restrict__ w_score,
                                    SmemA& a) {
    const int tid = threadIdx.x;
    __syncthreads();
    for (int h = tid; h < HH; h += NTHR) {
        float sacc = 0.0f;
#pragma unroll
        for (int sl = 0; sl < 4; sl++)
            sacc += g_pdp[(size_t)(sl * 64 + b) * HH + h];
        a.pds[h] = sacc;
        a.wss[h] = w_score[h];
    }
    __syncthreads();
    const int warp = tid >> 5, lane = tid & 31;
    float pd16[16], ws16[16];
    {
        const float4* ps = (const float4*)a.pds;
        const float4* wsv = (const float4*)a.wss;
#pragma unroll
        for (int jj = 0; jj < 2; jj++) {
            int base = (lane + 32 * jj) * 2;
            float4 p0 = ps[base], p1 = ps[base + 1];
            float4 w0 = wsv[base], w1 = wsv[base + 1];
            pd16[jj * 8 + 0] = p0.x; pd16[jj * 8 + 1] = p0.y;
            pd16[jj * 8 + 2] = p0.z; pd16[jj * 8 + 3] = p0.w;
            pd16[jj * 8 + 4] = p1.x; pd16[jj * 8 + 5] = p1.y;
            pd16[jj * 8 + 6] = p1.z; pd16[jj * 8 + 7] = p1.w;
            ws16[jj * 8 + 0] = w0.x; ws16[jj * 8 + 1] = w0.y;
            ws16[jj * 8 + 2] = w0.z; ws16[jj * 8 + 3] = w0.w;
            ws16[jj * 8 + 4] = w1.x; ws16[jj * 8 + 5] = w1.y;
            ws16[jj * 8 + 6] = w1.z; ws16[jj * 8 + 7] = w1.w;
        }
    }
#pragma unroll
    for (int it = 0; it < 8; it++) {
        int t = tc * 64 + warp * 8 + it;
        const uint4* row = (const uint4*)(g_peh + ((size_t)b * TE + t) * HH);
        float acc = 0.0f;
#pragma unroll
        for (int jj = 0; jj < 2; jj++) {
            uint4 v = row[lane + 32 * jj];
            const float* pd = &pd16[jj * 8];
            const float* ws = &ws16[jj * 8];
            float2 f;
            f = __half22float2(*(__half2*)&v.x);
            acc += ws[0] * fast_tanh(pd[0] + f.x) + ws[1] * fast_tanh(pd[1] + f.y);
            f = __half22float2(*(__half2*)&v.y);
            acc += ws[2] * fast_tanh(pd[2] + f.x) + ws[3] * fast_tanh(pd[3] + f.y);
            f = __half22float2(*(__half2*)&v.z);
            acc += ws[4] * fast_tanh(pd[4] + f.x) + ws[5] * fast_tanh(pd[5] + f.y);
            f = __half22float2(*(__half2*)&v.w);
            acc += ws[6] * fast_tanh(pd[6] + f.x) + ws[7] * fast_tanh(pd[7] + f.y);
        }
#pragma unroll
        for (int off = 16; off > 0; off >>= 1)
            acc += __shfl_down_sync(0xffffffffu, acc, off);
        if (lane == 0) g_e[b * TE + t] = acc;
    }
}

// ---------------- B2: softmax + x_hat (ctx part via H2 + xx fold + bias) --------
__device__ __noinline__ void xhat_job(int b, int half, const float* __restrict__ b_yattn,
                                      SmemA& a) {
    const int tid = threadIdx.x;
    __syncthreads();
    float ev = g_e[b * TE + tid];
    a.red[tid] = ev;
    __syncthreads();
    for (int s = 128; s > 0; s >>= 1) {
        if (tid < s) a.red[tid] = fmaxf(a.red[tid], a.red[tid + s]);
        __syncthreads();
    }
    float mx = a.red[0];
    __syncthreads();
    float p = __expf(ev - mx);
    a.red[tid] = p;
    __syncthreads();
    for (int s = 128; s > 0; s >>= 1) {
        if (tid < s) a.red[tid] += a.red[tid + s];
        __syncthreads();
    }
    float inv = 1.0f / a.red[0];
    a.ss[tid] = p * inv;
    __syncthreads();
    const int ml = tid & 127, th = tid >> 7;
    const int m = half * 128 + ml;
    const float* hb = g_h2 + ((size_t)b * TE + th * 128) * CIN + m;
    const float* ssp = &a.ss[th * 128];
    float a0 = 0, a1 = 0, a2 = 0, a3 = 0;
#pragma unroll 4
    for (int t = 0; t < 128; t += 4) {
        a0 += ssp[t + 0] * hb[(size_t)(t + 0) * CIN];
        a1 += ssp[t + 1] * hb[(size_t)(t + 1) * CIN];
        a2 += ssp[t + 2] * hb[(size_t)(t + 2) * CIN];
        a3 += ssp[t + 3] * hb[(size_t)(t + 3) * CIN];
    }
    __syncthreads();
    a.red[tid] = (a0 + a1) + (a2 + a3);
    __syncthreads();
    if (th == 0) {
        float v = a.red[tid] + a.red[tid + 128] + g_xp[b * CIN + m] + b_yattn[m];
        g_xhath[b * CIN + m] = __float2half_rn(v);
    }
}

// ---------------- epilogue: softmax + ctx quarter (from last-step g_e) ---------
__device__ __noinline__ void ctx_job(int b, int qm, SmemA& a) {
    const int tid = threadIdx.x;
    __syncthreads();
    float ev = g_e[b * TE + tid];
    a.red[tid] = ev;
    __syncthreads();
    for (int s = 128; s > 0; s >>= 1) {
        if (tid < s) a.red[tid] = fmaxf(a.red[tid], a.red[tid + s]);
        __syncthreads();
    }
    float mx = a.red[0];
    __syncthreads();
    float p = __expf(ev - mx);
    a.red[tid] = p;
    __syncthreads();
    for (int s = 128; s > 0; s >>= 1) {
        if (tid < s) a.red[tid] += a.red[tid + s];
        __syncthreads();
    }
    float inv = 1.0f / a.red[0];
    a.ss[tid] = p * inv;
    __syncthreads();
    const int ml = tid & 127, th = tid >> 7;
    const int m = qm * 128 + ml;
    const __half* hb = g_henh + ((size_t)b * TE + th * 128) * HH + m;
    const float* ssp = &a.ss[th * 128];
    float a0 = 0, a1 = 0;
#pragma unroll 4
    for (int t = 0; t < 128; t += 2) {
        a0 += ssp[t + 0] * __half2float(hb[(size_t)(t + 0) * HH]);
        a1 += ssp[t + 1] * __half2float(hb[(size_t)(t + 1) * HH]);
    }
    __syncthreads();
    a.red[tid] = a0 + a1;
    __syncthreads();
    if (th == 0)
        g_ctxh[b * HH + m] = __float2half_rn(a.red[tid] + a.red[tid + 128]);
}

// ---------------- prologue pack kernel ----------------
__global__ void k_pack(const float* __restrict__ x, const float* __restrict__ h_en,
                       const float* __restrict__ W_dec, const float* __restrict__ W_enc,
                       const float* __restrict__ W_yattn,
                       const float* __restrict__ W_ih, const float* __restrict__ W_hh,
                       const float* __restrict__ W_ff1, const float* __restrict__ W_ff2,
                       const float* __restrict__ W_ta, const float* __restrict__ W_tb,
                       const float* __restrict__ b_ff1, const float* __restrict__ b_ff2,
                       const float* __restrict__ b_ta, const float* __restrict__ b_tb,
                       const float* __restrict__ W_o1, const float* __restrict__ W_o2) {
    // reset barrier state (FIX: g_gen reset from thread 0, which exists)
    if (blockIdx.x == 0) {
        if (threadIdx.x == 0) g_gen = 0ull;
        if (threadIdx.x < 256 && (threadIdx.x & 15) == 0) g_cnt[threadIdx.x] = 0ull;
    }
    const int N1 = G4 * CAT;
    const int N2 = 3 * HH * CAT;
    const int N3 = 3 * HH;
    const int N4 = HH * 1024;
    const int N5 = CIN * CAT;
    const int N6 = HH * 1024;
    const int N7 = OUTN * HH;
    const int N8 = HH * HH;
    const int N9 = BB * LL * CIN;
    const int N10 = BB * TE * HH;
    const int T1 = N1, T2 = T1 + N2, T3 = T2 + N3, T4 = T3 + N4, T5 = T4 + N5;
    const int T6 = T5 + N6, T7 = T6 + N7, T8 = T7 + N8, T9 = T8 + N9;
    const int total = T9 + N10;
    for (int i = blockIdx.x * blockDim.x + threadIdx.x; i < total;
         i += gridDim.x * blockDim.x) {
        if (i < T1) {
            int nn = i / CAT, k = i % CAT;
            float v = (k < CIN) ? W_ih[nn * CIN + k] : W_hh[nn * HH + (k - CIN)];
            g_w6h[i] = __float2half_rn(v);
        } else if (i < T2) {
            int j = i - T1;
            int nn = j / CAT, k = j % CAT;
            int gate = nn / HH, u = nn % HH;
            float v;
            if (gate == 0)      v = W_ff1[u * CAT + k];
            else if (gate == 1) v = W_ff2[u * CAT + k];
            else                v = W_ta[u * CAT + k] + W_tb[u * CAT + k];
            g_w3h[j] = __float2half_rn(v);
        } else if (i < T3) {
            int nn = i - T2;
            int gate = nn / HH, u = nn % HH;
            g_b3[nn] = (gate == 0) ? b_ff1[u] : (gate == 1) ? b_ff2[u]
                                              : (b_ta[u] + b_tb[u]);
        } else if (i < T4) {
            int j = i - T3;
            g_wdh[j] = __float2half_rn(W_dec[j]);
        } else if (i < T5) {
            int j = i - T4;
            g_wyh[j] = __float2half_rn(W_yattn[j]);
        } else if (i < T6) {
            int j = i - T5;
            g_wo1h[j] = __float2half_rn(W_o1[j]);
        } else if (i < T7) {
            int j = i - T6;
            g_wo2h[j] = __float2half_rn(W_o2[j]);
        } else if (i < T8) {
            int j = i - T7;
            g_wench[j] = __float2half_rn(W_enc[j]);
        } else if (i < T9) {
            int j = i - T8;
            g_xh[j] = __float2half_rn(x[j]);
        } else {
            int j = i - T9;
            g_henh[j] = __float2half_rn(h_en[j]);
        }
    }
}

// ---------------- the persistent uber-kernel ----------------
__global__ void __launch_bounds__(NTHR, 2)
k_main(const float* __restrict__ b_enc, const float* __restrict__ w_score,
       const float* __restrict__ b_yattn, const float* __restrict__ b_ih,
       const float* __restrict__ b_o1, const float* __restrict__ b_o2,
       float* __restrict__ out, int write_state) {
    __shared__ Smem sm;
    const int bid = blockIdx.x;
    const int tid = threadIdx.x;
    const int gstep = NBLK * NTHR;
    unsigned long long bar_t = 0;

    // ---- P0: init states + proj_enc -> fp16 + H2 -> fp32 ----
    for (int idx = bid * NTHR + tid; idx < BB * HH; idx += gstep) {
        g_h[idx] = 0.0f; g_c[idx] = 0.0f;
        g_hh[idx] = __float2half_rn(0.0f);
        g_ch[idx] = __float2half_rn(0.0f);
    }
    for (int j = bid; j < 3072; j += NBLK) {
        if (j < 2048) {
            int mt = j >> 3, nt = j & 7;
            gemm_mma(g_henh + (size_t)mt * 64 * HH, HH,
                     g_wench + (size_t)(nt * 64) * HH, HH, HH,
                     nullptr, HH, g_peh + (size_t)mt * 64 * HH + nt * 64,
                     b_enc + nt * 64, sm.g);
        } else {
            int q = j - 2048;
            int mt = q >> 2, nt = q & 3;
            gemm_mma(g_henh + (size_t)mt * 64 * HH, HH,
                     g_wyh + (size_t)(nt * 64) * CAT + CIN, CAT, HH,
                     g_h2 + (size_t)mt * 64 * CIN + nt * 64, CIN, nullptr, nullptr, sm.g);
        }
    }
    GSYNC();

    for (int t = 0; t < LL; t++) {
        // ---- A: pd (8nt x 4ks k256 = 32) + zh (128) + xx (4, k256) = 164 jobs ----
        for (int j = bid; j < 164; j += NBLK) {
            if (j < 32) {
                int nt = j >> 2, ks = j & 3;
                const __half* A = (ks < 2) ? g_hh + ks * 256 : g_ch + (ks - 2) * 256;
                gemm_mma(A, HH, g_wdh + (size_t)(nt * 64) * 1024 + ks * 256, 1024, 256,
                         g_pdp + (size_t)ks * 64 * HH + nt * 64, HH, nullptr, nullptr, sm.g);
            } else if (j < 160) {
                int q = j - 32;
                int nt = q >> 2, ks = q & 3;
                gemm_mma(g_hh + ks * 128, HH,
                         g_w6h + (size_t)(nt * 64) * CAT + CIN + ks * 128, CAT, 128,
                         g_zp + (size_t)ks * 64 * G4 + nt * 64, G4, nullptr, nullptr, sm.g);
            } else {
                int nt = j - 160;
                gemm_mma(g_xh + (size_t)t * CIN, LL * CIN,
                         g_wyh + (size_t)(nt * 64) * CAT, CAT, 256,
                         g_xp + nt * 64, CIN, nullptr, nullptr, sm.g);
            }
        }
        GSYNC();
        // ---- B1: e-scores (64 b x 4 tc = 256 jobs) ----
        for (int j = bid; j < 256; j += NBLK) {
            escore(j >> 2, j & 3, w_score, sm.a);
        }
        GSYNC();
        // ---- B2: softmax + x_hat halves (128 jobs) ----
        for (int j = bid; j < 128; j += NBLK) {
            xhat_job(j >> 1, j & 1, b_yattn, sm.a);
        }
        GSYNC();
        // ---- D: zx (64, zp 4-5) + cfcx (48, fp 4-5) ----
        for (int j = bid; j < 112; j += NBLK) {
            if (j < 64) {
                int nt = j >> 1, ks = j & 1;
                gemm_mma(g_xhath + ks * 128, CIN,
                         g_w6h + (size_t)(nt * 64) * CAT + ks * 128, CAT, 128,
                         g_zp + (size_t)(4 + ks) * 64 * G4 + nt * 64, G4, nullptr, nullptr, sm.g);
            } else {
                int q = j - 64;
                int nt = q >> 1, ks = q & 1;
                gemm_mma(g_xhath + ks * 128, CIN,
                         g_w3h + (size_t)(nt * 64) * CAT + ks * 128, CAT, 128,
                         g_fp + (size_t)(4 + ks) * 64 * (3 * HH) + nt * 64, 3 * HH,
                         nullptr, nullptr, sm.g);
            }
        }
        GSYNC();
        // ---- E: LSTM pointwise (fold zp 0-5) ----
        for (int idx = bid * NTHR + tid; idx < BB * HH; idx += gstep) {
            int m = idx >> 9, u = idx & 511;
            float zi = b_ih[u], zg = b_ih[u + 512], zf = b_ih[u + 1024], zo = b_ih[u + 1536];
#pragma unroll
            for (int sl = 0; sl < 6; sl++) {
                const float* p = g_zp + (size_t)(sl * 64 + m) * G4;
                zi += p[u]; zg += p[u + 512]; zf += p[u + 1024]; zo += p[u + 1536];
            }
            float c_old = g_c[idx];
            float nc = c_old * sigm(zf + 1.0f) + tanhf(zi) * sigm(zg);
            g_c[idx] = nc;
            g_ch[idx] = __float2half_rn(nc);
            float hl = tanhf(nc) * sigm(zo);
            g_hlh[idx] = __float2half_rn(hl);
        }
        GSYNC();
        // ---- F: cfc h-part (96, fp 0-3) ----
        for (int j = bid; j < 96; j += NBLK) {
            int nt = j >> 2, ks = j & 3;
            gemm_mma(g_hlh + ks * 128, HH,
                     g_w3h + (size_t)(nt * 64) * CAT + CIN + ks * 128, CAT, 128,
                     g_fp + (size_t)ks * 64 * (3 * HH) + nt * 64, 3 * HH, nullptr, nullptr, sm.g);
        }
        GSYNC();
        // ---- G: CfC pointwise (fold fp 0-5) -> new h ----
        for (int idx = bid * NTHR + tid; idx < BB * HH; idx += gstep) {
            int m = idx >> 9, u = idx & 511;
            float f1 = g_b3[u], f2 = g_b3[u + 512], tg = g_b3[u + 1024];
#pragma unroll
            for (int sl = 0; sl < 6; sl++) {
                const float* p = g_fp + (size_t)(sl * 64 + m) * (3 * HH);
                f1 += p[u]; f2 += p[u + 512]; tg += p[u + 1024];
            }
            float ti = sigm(tg);
            float nh = tanhf(f1) * (1.0f - ti) + ti * tanhf(f2);
            g_h[idx] = nh;
            g_hh[idx] = __float2half_rn(nh);
        }
        GSYNC();
    }

    // ---- EP0: ctx from last-step scores (256 jobs) ----
    for (int j = bid; j < 256; j += NBLK) {
        ctx_job(j >> 2, j & 3, sm.a);
    }
    GSYNC();
    // ---- EP1: O1 GEMM ([h|ctx], K=1024): 64 jobs -> zp ----
    for (int j = bid; j < 64; j += NBLK) {
        int nt = j >> 3, ks = j & 7;
        const __half* A = (ks < 4) ? g_hh + ks * 128 : g_ctxh + (ks - 4) * 128;
        gemm_mma(A, HH, g_wo1h + (size_t)(nt * 64) * 1024 + ks * 128, 1024, 128,
                 g_zp + (size_t)ks * 64 * HH + nt * 64, HH, nullptr, nullptr, sm.g);
    }
    GSYNC();
    // ---- EP2: reduce 8 + leaky relu -> fp16 hid ----
    for (int idx = bid * NTHR + tid; idx < BB * HH; idx += gstep) {
        int m = idx >> 9, u = idx & 511;
        float s = b_o1[u];
#pragma unroll
        for (int sl = 0; sl < 8; sl++)
            s += g_zp[(size_t)(sl * 64 + m) * HH + u];
        g_hidh[idx] = __float2half_rn((s > 0.0f) ? s : 0.01f * s);
    }
    GSYNC();
    // ---- EP3: O2 GEMM (hid, K=512): 8 jobs -> fp ----
    for (int j = bid; j < 8; j += NBLK) {
        int nt = j >> 2, ks = j & 3;
        gemm_mma(g_hidh + ks * 128, HH,
                 g_wo2h + (size_t)(nt * 64) * HH + ks * 128, HH, 128,
                 g_fp + (size_t)ks * 64 * OUTN + nt * 64, OUTN, nullptr, nullptr, sm.g);
    }
    GSYNC();
    // ---- EP4: final reduce + bias (+ optional state copy) ----
    for (int idx = bid * NTHR + tid; idx < BB * OUTN; idx += gstep) {
        int m = idx >> 7, u = idx & 127;
        float s = b_o2[u];
#pragma unroll
        for (int sl = 0; sl < 4; sl++)
            s += g_fp[(size_t)(sl * 64 + m) * OUTN + u];
        out[idx] = s;
    }
    if (write_state) {
        for (int idx = bid * NTHR + tid; idx < BB * HH; idx += gstep) {
            out[BB * OUTN + idx] = g_h[idx];
            out[BB * OUTN + BB * HH + idx] = g_c[idx];
        }
    }
}

// ============================================================================
extern "C" void kernel_launch(void* const* d_in, const int* in_sizes, int n_in,
                              void* d_out, int out_size) {
    const float* x       = (const float*)d_in[0];
    const float* h_en    = (const float*)d_in[1];
    const float* W_dec   = (const float*)d_in[2];
    const float* W_enc   = (const float*)d_in[3];
    const float* b_enc   = (const float*)d_in[4];
    const float* w_score = (const float*)d_in[5];
    const float* W_yattn = (const float*)d_in[6];
    const float* b_yattn = (const float*)d_in[7];
    const float* W_ih    = (const float*)d_in[8];
    const float* b_ih    = (const float*)d_in[9];
    const float* W_hh    = (const float*)d_in[10];
    const float* W_ff1   = (const float*)d_in[11];
    const float* b_ff1   = (const float*)d_in[12];
    const float* W_ff2   = (const float*)d_in[13];
    const float* b_ff2   = (const float*)d_in[14];
    const float* W_ta    = (const float*)d_in[15];
    const float* b_ta    = (const float*)d_in[16];
    const float* W_tb    = (const float*)d_in[17];
    const float* b_tb    = (const float*)d_in[18];
    const float* W_o1    = (const float*)d_in[19];
    const float* b_o1    = (const float*)d_in[20];
    const float* W_o2    = (const float*)d_in[21];
    const float* b_o2    = (const float*)d_in[22];
    float* out = (float*)d_out;

    int write_state = (out_size >= BB * OUTN + 2 * BB * HH) ? 1 : 0;

    k_pack<<<512, 256>>>(x, h_en, W_dec, W_enc, W_yattn, W_ih, W_hh,
                         W_ff1, W_ff2, W_ta, W_tb,
                         b_ff1, b_ff2, b_ta, b_tb, W_o1, W_o2);
    k_main<<<NBLK, NTHR>>>(b_enc, w_score, b_yattn, b_ih,
                           b_o1, b_o2, out, write_state);
}

// round 16
// speedup vs baseline: 1.1382x; 1.1382x over previous
#include <cuda_runtime.h>
#include <cuda_fp16.h>
#include <cstdint>

#define BB   64
#define LL   128
#define TE   256
#define CIN  256
#define HH   512
#define CAT  768
#define G4   2048
#define OUTN 128
#define NBLK 288
#define NTHR 256

// ---------------- persistent device buffers ----------------
__device__ __half g_peh[(size_t)BB * TE * HH];   // proj_enc fp16 (16 MB)
__device__ __half g_henh[(size_t)BB * TE * HH];  // h_en fp16 (16 MB)
__device__ __half g_xh[(size_t)BB * LL * CIN];   // x fp16 (4 MB)
__device__ float g_h2[(size_t)BB * TE * CIN];    // h_en @ Wy_ctx^T (16 MB fp32)
__device__ float g_e[BB * TE];
__device__ float g_pdp[4 * 64 * HH];             // pd partials (4 slices k256)
__device__ float g_xp[64 * CIN];                 // xx partial (1 slice K=256)
__device__ float g_zp[6 * 64 * G4];              // z partials (zh:0-3, zx:4-5; epi O1)
__device__ float g_fp[6 * 64 * 3 * HH];          // cfc partials (h:0-3, x:4-5; epi O2)
__device__ float g_h[BB * HH];
__device__ float g_c[BB * HH];
// fp16 activation twins (GEMM A operands)
__device__ __half g_hh[BB * HH];
__device__ __half g_ch[BB * HH];
__device__ __half g_ctxh[BB * HH];
__device__ __half g_xhath[BB * CIN];
__device__ __half g_hlh[BB * HH];
__device__ __half g_hidh[BB * HH];
// fp16 weights
__device__ __half g_w6h[G4 * CAT];               // [W_ih | W_hh]
__device__ __half g_w3h[3 * HH * CAT];           // [ff1; ff2; ta+tb]
__device__ __half g_wdh[HH * 1024];              // W_dec
__device__ __half g_wyh[CIN * CAT];              // W_yattn
__device__ __half g_wo1h[HH * 1024];             // W_o1
__device__ __half g_wo2h[OUTN * HH];              // W_o2
__device__ __half g_wench[HH * HH];              // W_enc
__device__ float g_b3[3 * HH];
__device__ unsigned long long g_arr;             // monotonic barrier counter

// ---------------- helpers ----------------
__device__ __forceinline__ float fast_tanh(float x) {
    float y;
    asm("tanh.approx.f32 %0, %1;" : "=f"(y) : "f"(x));
    return y;
}
__device__ __forceinline__ float sigm(float x) {
    return 1.0f / (1.0f + __expf(-x));
}
__device__ __forceinline__ void cpa16(void* smem, const void* gmem) {
    unsigned s = (unsigned)__cvta_generic_to_shared(smem);
    asm volatile("cp.async.ca.shared.global [%0], [%1], 16;" :: "r"(s), "l"(gmem));
}

// ---------------- simple monotonic-counter global barrier (R13 design) --------
#define GSYNC() do {                                                     \
    __syncthreads();                                                     \
    if (threadIdx.x == 0) {                                              \
        __threadfence();                                                 \
        bar_t += NBLK;                                                   \
        atomicAdd(&g_arr, 1ull);                                         \
        while (*(volatile unsigned long long*)&g_arr < bar_t) { }        \
        __threadfence();                                                 \
    }                                                                    \
    __syncthreads();                                                     \
} while (0)

// ---------------- shared memory ----------------
struct SmemG { __half A[64][136]; __half W[64][136]; };   // 34.8 KB
struct SmemA { float pds[HH]; float wss[HH]; float ss[TE]; float red[NTHR]; };
union Smem { SmemG g; SmemA a; };

// ---------------- mma.sync m16n8k16 fp16 -> fp32 ----------------
__device__ __forceinline__ void mma16816(float* c, unsigned a0, unsigned a1,
                                         unsigned a2, unsigned a3,
                                         unsigned b0, unsigned b1) {
    asm volatile(
        "mma.sync.aligned.m16n8k16.row.col.f32.f16.f16.f32 "
        "{%0,%1,%2,%3}, {%4,%5,%6,%7}, {%8,%9}, {%0,%1,%2,%3};"
        : "+f"(c[0]), "+f"(c[1]), "+f"(c[2]), "+f"(c[3])
        : "r"(a0), "r"(a1), "r"(a2), "r"(a3), "r"(b0), "r"(b1));
}

// ---------------- 64x64xK GEMM job, 256 threads, cp.async smem staging ---------
__device__ __noinline__ void gemm_mma(const __half* __restrict__ A, int lda,
                                      const __half* __restrict__ W, int ldw,
                                      int klen,
                                      float* __restrict__ dst, int dstr,
                                      __half* __restrict__ dsth,
                                      const float* __restrict__ bias, SmemG& s) {
    const int tid  = threadIdx.x;
    const int lane = tid & 31, wid = tid >> 5;
    const int wm = wid >> 1, wn = wid & 1;      // 4 x 2 warp grid -> m16 x n32
    const int gr = lane >> 2, kc = (lane & 3) * 2;
    const int lr = tid >> 2;                    // staging row 0..63
    const int lu = tid & 3;                     // staging unit group
    float c[4][4];
#pragma unroll
    for (int nf = 0; nf < 4; nf++)
#pragma unroll
        for (int i = 0; i < 4; i++) c[nf][i] = 0.0f;

    for (int kb = 0; kb < klen; kb += 128) {
        __syncthreads();   // previous chunk's smem reads complete
        const __half* Ar = A + (size_t)lr * lda + kb;
        const __half* Wr = W + (size_t)lr * ldw + kb;
#pragma unroll
        for (int u = 0; u < 4; u++) {
            int unit = lu + 4 * u;
            cpa16(&s.A[lr][unit * 8], Ar + unit * 8);
            cpa16(&s.W[lr][unit * 8], Wr + unit * 8);
        }
        asm volatile("cp.async.commit_group;");
        asm volatile("cp.async.wait_group 0;" ::: "memory");
        __syncthreads();
#pragma unroll
        for (int k0 = 0; k0 < 128; k0 += 16) {
            unsigned a0 = *(const unsigned*)&s.A[wm * 16 + gr][k0 + kc];
            unsigned a1 = *(const unsigned*)&s.A[wm * 16 + gr + 8][k0 + kc];
            unsigned a2 = *(const unsigned*)&s.A[wm * 16 + gr][k0 + kc + 8];
            unsigned a3 = *(const unsigned*)&s.A[wm * 16 + gr + 8][k0 + kc + 8];
#pragma unroll
            for (int nf = 0; nf < 4; nf++) {
                unsigned b0 = *(const unsigned*)&s.W[wn * 32 + nf * 8 + gr][k0 + kc];
                unsigned b1 = *(const unsigned*)&s.W[wn * 32 + nf * 8 + gr][k0 + kc + 8];
                mma16816(c[nf], a0, a1, a2, a3, b0, b1);
            }
        }
    }
    const int row = wm * 16 + gr;
#pragma unroll
    for (int nf = 0; nf < 4; nf++) {
        int col = wn * 32 + nf * 8 + kc;
        float add0 = 0.0f, add1 = 0.0f;
        if (bias) { add0 = bias[col]; add1 = bias[col + 1]; }
        float v0 = c[nf][0] + add0, v1 = c[nf][1] + add1;
        float v2 = c[nf][2] + add0, v3 = c[nf][3] + add1;
        if (dsth) {
            *(__half2*)(dsth + (size_t)row * dstr + col) = __floats2half2_rn(v0, v1);
            *(__half2*)(dsth + (size_t)(row + 8) * dstr + col) = __floats2half2_rn(v2, v3);
        } else {
            *(float2*)(dst + (size_t)row * dstr + col) = make_float2(v0, v1);
            *(float2*)(dst + (size_t)(row + 8) * dstr + col) = make_float2(v2, v3);
        }
    }
}

// ---------------- B1: e-scores for (batch b, t-chunk tc of 64) ----------------
__device__ __noinline__ void escore(int b, int tc, const float* __restrict__ w_score,
                                    SmemA& a) {
    const int tid = threadIdx.x;
    __syncthreads();
    for (int h = tid; h < HH; h += NTHR) {
        float sacc = 0.0f;
#pragma unroll
        for (int sl = 0; sl < 4; sl++)
            sacc += g_pdp[(size_t)(sl * 64 + b) * HH + h];
        a.pds[h] = sacc;
        a.wss[h] = w_score[h];
    }
    __syncthreads();
    const int warp = tid >> 5, lane = tid & 31;
    float pd16[16], ws16[16];
    {
        const float4* ps = (const float4*)a.pds;
        const float4* wsv = (const float4*)a.wss;
#pragma unroll
        for (int jj = 0; jj < 2; jj++) {
            int base = (lane + 32 * jj) * 2;
            float4 p0 = ps[base], p1 = ps[base + 1];
            float4 w0 = wsv[base], w1 = wsv[base + 1];
            pd16[jj * 8 + 0] = p0.x; pd16[jj * 8 + 1] = p0.y;
            pd16[jj * 8 + 2] = p0.z; pd16[jj * 8 + 3] = p0.w;
            pd16[jj * 8 + 4] = p1.x; pd16[jj * 8 + 5] = p1.y;
            pd16[jj * 8 + 6] = p1.z; pd16[jj * 8 + 7] = p1.w;
            ws16[jj * 8 + 0] = w0.x; ws16[jj * 8 + 1] = w0.y;
            ws16[jj * 8 + 2] = w0.z; ws16[jj * 8 + 3] = w0.w;
            ws16[jj * 8 + 4] = w1.x; ws16[jj * 8 + 5] = w1.y;
            ws16[jj * 8 + 6] = w1.z; ws16[jj * 8 + 7] = w1.w;
        }
    }
#pragma unroll
    for (int it = 0; it < 8; it++) {
        int t = tc * 64 + warp * 8 + it;
        const uint4* row = (const uint4*)(g_peh + ((size_t)b * TE + t) * HH);
        float acc = 0.0f;
#pragma unroll
        for (int jj = 0; jj < 2; jj++) {
            uint4 v = row[lane + 32 * jj];
            const float* pd = &pd16[jj * 8];
            const float* ws = &ws16[jj * 8];
            float2 f;
            f = __half22float2(*(__half2*)&v.x);
            acc += ws[0] * fast_tanh(pd[0] + f.x) + ws[1] * fast_tanh(pd[1] + f.y);
            f = __half22float2(*(__half2*)&v.y);
            acc += ws[2] * fast_tanh(pd[2] + f.x) + ws[3] * fast_tanh(pd[3] + f.y);
            f = __half22float2(*(__half2*)&v.z);
            acc += ws[4] * fast_tanh(pd[4] + f.x) + ws[5] * fast_tanh(pd[5] + f.y);
            f = __half22float2(*(__half2*)&v.w);
            acc += ws[6] * fast_tanh(pd[6] + f.x) + ws[7] * fast_tanh(pd[7] + f.y);
        }
#pragma unroll
        for (int off = 16; off > 0; off >>= 1)
            acc += __shfl_down_sync(0xffffffffu, acc, off);
        if (lane == 0) g_e[b * TE + t] = acc;
    }
}

// ---------------- B2: softmax + x_hat (ctx part via H2 + xx fold + bias) --------
__device__ __noinline__ void xhat_job(int b, int half, const float* __restrict__ b_yattn,
                                      SmemA& a) {
    const int tid = threadIdx.x;
    __syncthreads();
    float ev = g_e[b * TE + tid];
    a.red[tid] = ev;
    __syncthreads();
    for (int s = 128; s > 0; s >>= 1) {
        if (tid < s) a.red[tid] = fmaxf(a.red[tid], a.red[tid + s]);
        __syncthreads();
    }
    float mx = a.red[0];
    __syncthreads();
    float p = __expf(ev - mx);
    a.red[tid] = p;
    __syncthreads();
    for (int s = 128; s > 0; s >>= 1) {
        if (tid < s) a.red[tid] += a.red[tid + s];
        __syncthreads();
    }
    float inv = 1.0f / a.red[0];
    a.ss[tid] = p * inv;
    __syncthreads();
    const int ml = tid & 127, th = tid >> 7;
    const int m = half * 128 + ml;
    const float* hb = g_h2 + ((size_t)b * TE + th * 128) * CIN + m;
    const float* ssp = &a.ss[th * 128];
    float a0 = 0, a1 = 0, a2 = 0, a3 = 0;
#pragma unroll 4
    for (int t = 0; t < 128; t += 4) {
        a0 += ssp[t + 0] * hb[(size_t)(t + 0) * CIN];
        a1 += ssp[t + 1] * hb[(size_t)(t + 1) * CIN];
        a2 += ssp[t + 2] * hb[(size_t)(t + 2) * CIN];
        a3 += ssp[t + 3] * hb[(size_t)(t + 3) * CIN];
    }
    __syncthreads();
    a.red[tid] = (a0 + a1) + (a2 + a3);
    __syncthreads();
    if (th == 0) {
        float v = a.red[tid] + a.red[tid + 128] + g_xp[b * CIN + m] + b_yattn[m];
        g_xhath[b * CIN + m] = __float2half_rn(v);
    }
}

// ---------------- epilogue: softmax + ctx quarter (from last-step g_e) ---------
__device__ __noinline__ void ctx_job(int b, int qm, SmemA& a) {
    const int tid = threadIdx.x;
    __syncthreads();
    float ev = g_e[b * TE + tid];
    a.red[tid] = ev;
    __syncthreads();
    for (int s = 128; s > 0; s >>= 1) {
        if (tid < s) a.red[tid] = fmaxf(a.red[tid], a.red[tid + s]);
        __syncthreads();
    }
    float mx = a.red[0];
    __syncthreads();
    float p = __expf(ev - mx);
    a.red[tid] = p;
    __syncthreads();
    for (int s = 128; s > 0; s >>= 1) {
        if (tid < s) a.red[tid] += a.red[tid + s];
        __syncthreads();
    }
    float inv = 1.0f / a.red[0];
    a.ss[tid] = p * inv;
    __syncthreads();
    const int ml = tid & 127, th = tid >> 7;
    const int m = qm * 128 + ml;
    const __half* hb = g_henh + ((size_t)b * TE + th * 128) * HH + m;
    const float* ssp = &a.ss[th * 128];
    float a0 = 0, a1 = 0;
#pragma unroll 4
    for (int t = 0; t < 128; t += 2) {
        a0 += ssp[t + 0] * __half2float(hb[(size_t)(t + 0) * HH]);
        a1 += ssp[t + 1] * __half2float(hb[(size_t)(t + 1) * HH]);
    }
    __syncthreads();
    a.red[tid] = a0 + a1;
    __syncthreads();
    if (th == 0)
        g_ctxh[b * HH + m] = __float2half_rn(a.red[tid] + a.red[tid + 128]);
}

// ---------------- prologue pack kernel ----------------
__global__ void k_pack(const float* __restrict__ x, const float* __restrict__ h_en,
                       const float* __restrict__ W_dec, const float* __restrict__ W_enc,
                       const float* __restrict__ W_yattn,
                       const float* __restrict__ W_ih, const float* __restrict__ W_hh,
                       const float* __restrict__ W_ff1, const float* __restrict__ W_ff2,
                       const float* __restrict__ W_ta, const float* __restrict__ W_tb,
                       const float* __restrict__ b_ff1, const float* __restrict__ b_ff2,
                       const float* __restrict__ b_ta, const float* __restrict__ b_tb,
                       const float* __restrict__ W_o1, const float* __restrict__ W_o2) {
    if (blockIdx.x == 0 && threadIdx.x == 0) g_arr = 0ull;
    const int N1 = G4 * CAT;
    const int N2 = 3 * HH * CAT;
    const int N3 = 3 * HH;
    const int N4 = HH * 1024;
    const int N5 = CIN * CAT;
    const int N6 = HH * 1024;
    const int N7 = OUTN * HH;
    const int N8 = HH * HH;
    const int N9 = BB * LL * CIN;
    const int N10 = BB * TE * HH;
    const int T1 = N1, T2 = T1 + N2, T3 = T2 + N3, T4 = T3 + N4, T5 = T4 + N5;
    const int T6 = T5 + N6, T7 = T6 + N7, T8 = T7 + N8, T9 = T8 + N9;
    const int total = T9 + N10;
    for (int i = blockIdx.x * blockDim.x + threadIdx.x; i < total;
         i += gridDim.x * blockDim.x) {
        if (i < T1) {
            int nn = i / CAT, k = i % CAT;
            float v = (k < CIN) ? W_ih[nn * CIN + k] : W_hh[nn * HH + (k - CIN)];
            g_w6h[i] = __float2half_rn(v);
        } else if (i < T2) {
            int j = i - T1;
            int nn = j / CAT, k = j % CAT;
            int gate = nn / HH, u = nn % HH;
            float v;
            if (gate == 0)      v = W_ff1[u * CAT + k];
            else if (gate == 1) v = W_ff2[u * CAT + k];
            else                v = W_ta[u * CAT + k] + W_tb[u * CAT + k];
            g_w3h[j] = __float2half_rn(v);
        } else if (i < T3) {
            int nn = i - T2;
            int gate = nn / HH, u = nn % HH;
            g_b3[nn] = (gate == 0) ? b_ff1[u] : (gate == 1) ? b_ff2[u]
                                              : (b_ta[u] + b_tb[u]);
        } else if (i < T4) {
            int j = i - T3;
            g_wdh[j] = __float2half_rn(W_dec[j]);
        } else if (i < T5) {
            int j = i - T4;
            g_wyh[j] = __float2half_rn(W_yattn[j]);
        } else if (i < T6) {
            int j = i - T5;
            g_wo1h[j] = __float2half_rn(W_o1[j]);
        } else if (i < T7) {
            int j = i - T6;
            g_wo2h[j] = __float2half_rn(W_o2[j]);
        } else if (i < T8) {
            int j = i - T7;
            g_wench[j] = __float2half_rn(W_enc[j]);
        } else if (i < T9) {
            int j = i - T8;
            g_xh[j] = __float2half_rn(x[j]);
        } else {
            int j = i - T9;
            g_henh[j] = __float2half_rn(h_en[j]);
        }
    }
}

// ---------------- the persistent uber-kernel ----------------
__global__ void __launch_bounds__(NTHR, 2)
k_main(const float* __restrict__ b_enc, const float* __restrict__ w_score,
       const float* __restrict__ b_yattn, const float* __restrict__ b_ih,
       const float* __restrict__ b_o1, const float* __restrict__ b_o2,
       float* __restrict__ out, int write_state) {
    __shared__ Smem sm;
    const int bid = blockIdx.x;
    const int tid = threadIdx.x;
    const int gstep = NBLK * NTHR;
    unsigned long long bar_t = 0;

    // ---- P0: init states + proj_enc -> fp16 + H2 -> fp32 ----
    for (int idx = bid * NTHR + tid; idx < BB * HH; idx += gstep) {
        g_h[idx] = 0.0f; g_c[idx] = 0.0f;
        g_hh[idx] = __float2half_rn(0.0f);
        g_ch[idx] = __float2half_rn(0.0f);
    }
    for (int j = bid; j < 3072; j += NBLK) {
        if (j < 2048) {
            int mt = j >> 3, nt = j & 7;
            gemm_mma(g_henh + (size_t)mt * 64 * HH, HH,
                     g_wench + (size_t)(nt * 64) * HH, HH, HH,
                     nullptr, HH, g_peh + (size_t)mt * 64 * HH + nt * 64,
                     b_enc + nt * 64, sm.g);
        } else {
            int q = j - 2048;
            int mt = q >> 2, nt = q & 3;
            gemm_mma(g_henh + (size_t)mt * 64 * HH, HH,
                     g_wyh + (size_t)(nt * 64) * CAT + CIN, CAT, HH,
                     g_h2 + (size_t)mt * 64 * CIN + nt * 64, CIN, nullptr, nullptr, sm.g);
        }
    }
    GSYNC();

    for (int t = 0; t < LL; t++) {
        // ---- A: pd (8nt x 4ks k256 = 32) + zh (128) + xx (4, k256) = 164 jobs ----
        for (int j = bid; j < 164; j += NBLK) {
            if (j < 32) {
                int nt = j >> 2, ks = j & 3;
                const __half* A = (ks < 2) ? g_hh + ks * 256 : g_ch + (ks - 2) * 256;
                gemm_mma(A, HH, g_wdh + (size_t)(nt * 64) * 1024 + ks * 256, 1024, 256,
                         g_pdp + (size_t)ks * 64 * HH + nt * 64, HH, nullptr, nullptr, sm.g);
            } else if (j < 160) {
                int q = j - 32;
                int nt = q >> 2, ks = q & 3;
                gemm_mma(g_hh + ks * 128, HH,
                         g_w6h + (size_t)(nt * 64) * CAT + CIN + ks * 128, CAT, 128,
                         g_zp + (size_t)ks * 64 * G4 + nt * 64, G4, nullptr, nullptr, sm.g);
            } else {
                int nt = j - 160;
                gemm_mma(g_xh + (size_t)t * CIN, LL * CIN,
                         g_wyh + (size_t)(nt * 64) * CAT, CAT, 256,
                         g_xp + nt * 64, CIN, nullptr, nullptr, sm.g);
            }
        }
        GSYNC();
        // ---- B1: e-scores (64 b x 4 tc = 256 jobs) ----
        for (int j = bid; j < 256; j += NBLK) {
            escore(j >> 2, j & 3, w_score, sm.a);
        }
        GSYNC();
        // ---- B2: softmax + x_hat halves (128 jobs) ----
        for (int j = bid; j < 128; j += NBLK) {
            xhat_job(j >> 1, j & 1, b_yattn, sm.a);
        }
        GSYNC();
        // ---- D: zx (64, zp 4-5) + cfcx (48, fp 4-5) ----
        for (int j = bid; j < 112; j += NBLK) {
            if (j < 64) {
                int nt = j >> 1, ks = j & 1;
                gemm_mma(g_xhath + ks * 128, CIN,
                         g_w6h + (size_t)(nt * 64) * CAT + ks * 128, CAT, 128,
                         g_zp + (size_t)(4 + ks) * 64 * G4 + nt * 64, G4, nullptr, nullptr, sm.g);
            } else {
                int q = j - 64;
                int nt = q >> 1, ks = q & 1;
                gemm_mma(g_xhath + ks * 128, CIN,
                         g_w3h + (size_t)(nt * 64) * CAT + ks * 128, CAT, 128,
                         g_fp + (size_t)(4 + ks) * 64 * (3 * HH) + nt * 64, 3 * HH,
                         nullptr, nullptr, sm.g);
            }
        }
        GSYNC();
        // ---- E: LSTM pointwise (fold zp 0-5) ----
        for (int idx = bid * NTHR + tid; idx < BB * HH; idx += gstep) {
            int m = idx >> 9, u = idx & 511;
            float zi = b_ih[u], zg = b_ih[u + 512], zf = b_ih[u + 1024], zo = b_ih[u + 1536];
#pragma unroll
            for (int sl = 0; sl < 6; sl++) {
                const float* p = g_zp + (size_t)(sl * 64 + m) * G4;
                zi += p[u]; zg += p[u + 512]; zf += p[u + 1024]; zo += p[u + 1536];
            }
            float c_old = g_c[idx];
            float nc = c_old * sigm(zf + 1.0f) + tanhf(zi) * sigm(zg);
            g_c[idx] = nc;
            g_ch[idx] = __float2half_rn(nc);
            float hl = tanhf(nc) * sigm(zo);
            g_hlh[idx] = __float2half_rn(hl);
        }
        GSYNC();
        // ---- F: cfc h-part (96, fp 0-3) ----
        for (int j = bid; j < 96; j += NBLK) {
            int nt = j >> 2, ks = j & 3;
            gemm_mma(g_hlh + ks * 128, HH,
                     g_w3h + (size_t)(nt * 64) * CAT + CIN + ks * 128, CAT, 128,
                     g_fp + (size_t)ks * 64 * (3 * HH) + nt * 64, 3 * HH, nullptr, nullptr, sm.g);
        }
        GSYNC();
        // ---- G: CfC pointwise (fold fp 0-5) -> new h ----
        for (int idx = bid * NTHR + tid; idx < BB * HH; idx += gstep) {
            int m = idx >> 9, u = idx & 511;
            float f1 = g_b3[u], f2 = g_b3[u + 512], tg = g_b3[u + 1024];
#pragma unroll
            for (int sl = 0; sl < 6; sl++) {
                const float* p = g_fp + (size_t)(sl * 64 + m) * (3 * HH);
                f1 += p[u]; f2 += p[u + 512]; tg += p[u + 1024];
            }
            float ti = sigm(tg);
            float nh = tanhf(f1) * (1.0f - ti) + ti * tanhf(f2);
            g_h[idx] = nh;
            g_hh[idx] = __float2half_rn(nh);
        }
        GSYNC();
    }

    // ---- EP0: ctx from last-step scores (256 jobs) ----
    for (int j = bid; j < 256; j += NBLK) {
        ctx_job(j >> 2, j & 3, sm.a);
    }
    GSYNC();
    // ---- EP1: O1 GEMM ([h|ctx], K=1024): 64 jobs -> zp ----
    for (int j = bid; j < 64; j += NBLK) {
        int nt = j >> 3, ks = j & 7;
        const __half* A = (ks < 4) ? g_hh + ks * 128 : g_ctxh + (ks - 4) * 128;
        gemm_mma(A, HH, g_wo1h + (size_t)(nt * 64) * 1024 + ks * 128, 1024, 128,
                 g_zp + (size_t)ks * 64 * HH + nt * 64, HH, nullptr, nullptr, sm.g);
    }
    GSYNC();
    // ---- EP2: reduce 8 + leaky relu -> fp16 hid ----
    for (int idx = bid * NTHR + tid; idx < BB * HH; idx += gstep) {
        int m = idx >> 9, u = idx & 511;
        float s = b_o1[u];
#pragma unroll
        for (int sl = 0; sl < 8; sl++)
            s += g_zp[(size_t)(sl * 64 + m) * HH + u];
        g_hidh[idx] = __float2half_rn((s > 0.0f) ? s : 0.01f * s);
    }
    GSYNC();
    // ---- EP3: O2 GEMM (hid, K=512): 8 jobs -> fp ----
    for (int j = bid; j < 8; j += NBLK) {
        int nt = j >> 2, ks = j & 3;
        gemm_mma(g_hidh + ks * 128, HH,
                 g_wo2h + (size_t)(nt * 64) * HH + ks * 128, HH, 128,
                 g_fp + (size_t)ks * 64 * OUTN + nt * 64, OUTN, nullptr, nullptr, sm.g);
    }
    GSYNC();
    // ---- EP4: final reduce + bias (+ optional state copy) ----
    for (int idx = bid * NTHR + tid; idx < BB * OUTN; idx += gstep) {
        int m = idx >> 7, u = idx & 127;
        float s = b_o2[u];
#pragma unroll
        for (int sl = 0; sl < 4; sl++)
            s += g_fp[(size_t)(sl * 64 + m) * OUTN + u];
        out[idx] = s;
    }
    if (write_state) {
        for (int idx = bid * NTHR + tid; idx < BB * HH; idx += gstep) {
            out[BB * OUTN + idx] = g_h[idx];
            out[BB * OUTN + BB * HH + idx] = g_c[idx];
        }
    }
}

// ============================================================================
extern "C" void kernel_launch(void* const* d_in, const int* in_sizes, int n_in,
                              void* d_out, int out_size) {
    const float* x       = (const float*)d_in[0];
    const float* h_en    = (const float*)d_in[1];
    const float* W_dec   = (const float*)d_in[2];
    const float* W_enc   = (const float*)d_in[3];
    const float* b_enc   = (const float*)d_in[4];
    const float* w_score = (const float*)d_in[5];
    const float* W_yattn = (const float*)d_in[6];
    const float* b_yattn = (const float*)d_in[7];
    const float* W_ih    = (const float*)d_in[8];
    const float* b_ih    = (const float*)d_in[9];
    const float* W_hh    = (const float*)d_in[10];
    const float* W_ff1   = (const float*)d_in[11];
    const float* b_ff1   = (const float*)d_in[12];
    const float* W_ff2   = (const float*)d_in[13];
    const float* b_ff2   = (const float*)d_in[14];
    const float* W_ta    = (const float*)d_in[15];
    const float* b_ta    = (const float*)d_in[16];
    const float* W_tb    = (const float*)d_in[17];
    const float* b_tb    = (const float*)d_in[18];
    const float* W_o1    = (const float*)d_in[19];
    const float* b_o1    = (const float*)d_in[20];
    const float* W_o2    = (const float*)d_in[21];
    const float* b_o2    = (const float*)d_in[22];
    float* out = (float*)d_out;

    int write_state = (out_size >= BB * OUTN + 2 * BB * HH) ? 1 : 0;

    k_pack<<<512, 256>>>(x, h_en, W_dec, W_enc, W_yattn, W_ih, W_hh,
                         W_ff1, W_ff2, W_ta, W_tb,
                         b_ff1, b_ff2, b_ta, b_tb, W_o1, W_o2);
    k_main<<<NBLK, NTHR>>>(b_enc, w_score, b_yattn, b_ih,
                           b_o1, b_o2, out, write_state);
}